// round 14
// baseline (speedup 1.0000x reference)
#include <cuda_runtime.h>
#include <cuda_bf16.h>
#include <math.h>
#include <stdint.h>

#define BB 2
#define TT 2048
#define DD 2048
#define HH 16
#define DHD 128
#define DC 384
#define NROWS (BB*TT)        // 4096
#define NC 32
#define CL (TT/NC)           // 64

// ---------------- scratch (device globals: no runtime allocation allowed) ----
__device__ float g_q[NROWS*DD];
__device__ float g_k[NROWS*DD];
__device__ float g_p[NROWS*DD];
__device__ float g_g[NROWS*DD];
__device__ float g_clockbuf[NROWS*HH];
__device__ float g_logclock[NROWS*HH];
__device__ float g_part_pm[BB*HH*NC*DHD];
__device__ float g_part_ps[BB*HH*NC*DHD];
__device__ float g_part_gs[BB*HH*NC*DHD];
__device__ float g_part_cs[BB*HH*NC*DHD];

// bf16 split operands
__device__ __align__(16) __nv_bfloat16 g_xh[(size_t)NROWS*DD];
__device__ __align__(16) __nv_bfloat16 g_xl[(size_t)NROWS*DD];
__device__ __align__(16) __nv_bfloat16 g_ah[(size_t)NROWS*DD];   // attention out hi
__device__ __align__(16) __nv_bfloat16 g_al[(size_t)NROWS*DD];   // attention out lo
__device__ __align__(16) __nv_bfloat16 g_vh[(size_t)NROWS*DD];
__device__ __align__(16) __nv_bfloat16 g_vl[(size_t)NROWS*DD];
// fused projection B: [Wq Wk Wv Wp Wg | W_clock^T padded to 128 rows]
#define FUSED_ROWS (5*DD + 128)      // 10368
__device__ __align__(16) __nv_bfloat16 g_wth[(size_t)FUSED_ROWS*DD];
__device__ __align__(16) __nv_bfloat16 g_wtl[(size_t)FUSED_ROWS*DD];
__device__ __align__(16) __nv_bfloat16 g_wch[(size_t)DD*DD];     // Wc^T hi
__device__ __align__(16) __nv_bfloat16 g_wcl[(size_t)DD*DD];     // Wc^T lo
__device__ __align__(16) __nv_bfloat16 g_qch[(size_t)NROWS*HH*DC];
__device__ __align__(16) __nv_bfloat16 g_qcl[(size_t)NROWS*HH*DC];
__device__ __align__(16) __nv_bfloat16 g_kch[(size_t)NROWS*HH*DC];
__device__ __align__(16) __nv_bfloat16 g_kcl[(size_t)NROWS*HH*DC];

__device__ __forceinline__ float softplus_f(float x) {
    return fmaxf(x, 0.f) + log1pf(expf(-fabsf(x)));
}
__device__ __forceinline__ float softplus_fast(float x) {
    return fmaxf(x, 0.f) + __logf(1.f + __expf(-fabsf(x)));
}

// ==================== warp-mma helpers (family-common PTX) ===================
__device__ __forceinline__ uint32_t smem_u32(const void* p) {
    uint32_t a;
    asm("{ .reg .u64 t; cvta.to.shared.u64 t, %1; cvt.u32.u64 %0, t; }"
        : "=r"(a) : "l"(p));
    return a;
}
__device__ __forceinline__ void ldsm4(uint32_t r[4], uint32_t a) {
    asm volatile("ldmatrix.sync.aligned.m8n8.x4.shared.b16 {%0,%1,%2,%3}, [%4];"
        : "=r"(r[0]), "=r"(r[1]), "=r"(r[2]), "=r"(r[3]) : "r"(a));
}
__device__ __forceinline__ void ldsm4t(uint32_t r[4], uint32_t a) {
    asm volatile("ldmatrix.sync.aligned.m8n8.x4.trans.shared.b16 {%0,%1,%2,%3}, [%4];"
        : "=r"(r[0]), "=r"(r[1]), "=r"(r[2]), "=r"(r[3]) : "r"(a));
}
__device__ __forceinline__ void mma_bf(float c[4], const uint32_t a[4],
                                       uint32_t b0, uint32_t b1) {
    asm volatile(
        "mma.sync.aligned.m16n8k16.row.col.f32.bf16.bf16.f32 "
        "{%0,%1,%2,%3}, {%4,%5,%6,%7}, {%8,%9}, {%0,%1,%2,%3};"
        : "+f"(c[0]), "+f"(c[1]), "+f"(c[2]), "+f"(c[3])
        : "r"(a[0]), "r"(a[1]), "r"(a[2]), "r"(a[3]), "r"(b0), "r"(b1));
}
__device__ __forceinline__ void packsplit(float x, float y, uint32_t& hi, uint32_t& lo) {
    __nv_bfloat16 hx = __float2bfloat16_rn(x), hy = __float2bfloat16_rn(y);
    __nv_bfloat162 h2; h2.x = hx; h2.y = hy;
    __nv_bfloat162 l2;
    l2.x = __float2bfloat16_rn(x - __bfloat162float(hx));
    l2.y = __float2bfloat16_rn(y - __bfloat162float(hy));
    hi = *(uint32_t*)&h2; lo = *(uint32_t*)&l2;
}
#define CP16(dst, src) asm volatile("cp.async.cg.shared.global [%0], [%1], 16;" :: "r"(dst), "l"(src))
#define CP_COMMIT() asm volatile("cp.async.commit_group;" ::: "memory")
#define CP_WAIT0()  asm volatile("cp.async.wait_group 0;" ::: "memory")
#define CP_WAIT1()  asm volatile("cp.async.wait_group 1;" ::: "memory")

// ==================== split conversion kernels ==============================
__global__ void __launch_bounds__(256) conv_split(
    const float4* __restrict__ src, uint2* __restrict__ hi, uint2* __restrict__ lo, int n4)
{
    int i = blockIdx.x * 256 + threadIdx.x;
    if (i >= n4) return;
    float4 v = src[i];
    __nv_bfloat16 h0 = __float2bfloat16_rn(v.x), h1 = __float2bfloat16_rn(v.y);
    __nv_bfloat16 h2 = __float2bfloat16_rn(v.z), h3 = __float2bfloat16_rn(v.w);
    __nv_bfloat16 l0 = __float2bfloat16_rn(v.x - __bfloat162float(h0));
    __nv_bfloat16 l1 = __float2bfloat16_rn(v.y - __bfloat162float(h1));
    __nv_bfloat16 l2 = __float2bfloat16_rn(v.z - __bfloat162float(h2));
    __nv_bfloat16 l3 = __float2bfloat16_rn(v.w - __bfloat162float(h3));
    hi[i] = make_uint2((uint32_t)__bfloat16_as_ushort(h0) | ((uint32_t)__bfloat16_as_ushort(h1) << 16),
                       (uint32_t)__bfloat16_as_ushort(h2) | ((uint32_t)__bfloat16_as_ushort(h3) << 16));
    lo[i] = make_uint2((uint32_t)__bfloat16_as_ushort(l0) | ((uint32_t)__bfloat16_as_ushort(l1) << 16),
                       (uint32_t)__bfloat16_as_ushort(l2) | ((uint32_t)__bfloat16_as_ushort(l3) << 16));
}

// W[K][N] fp32 -> WT[N][K] bf16 hi/lo, batched over 5 weights via blockIdx.z
struct W5 { const float* w[5]; };
__global__ void __launch_bounds__(256) trans_split5(
    W5 ws, __nv_bfloat16* __restrict__ th, __nv_bfloat16* __restrict__ tl)
{
    __shared__ float t[32][33];
    int j = blockIdx.z;
    const float* W = ws.w[j];
    th += (size_t)j * DD * DD;
    tl += (size_t)j * DD * DD;
    int r0 = blockIdx.y * 32, c0 = blockIdx.x * 32;
    int xx = threadIdx.x & 31, yy = threadIdx.x >> 5;
    for (int rr = yy; rr < 32; rr += 8)
        t[rr][xx] = W[(size_t)(r0 + rr) * DD + c0 + xx];
    __syncthreads();
    for (int rr = yy; rr < 32; rr += 8) {
        float v = t[xx][rr];
        __nv_bfloat16 h = __float2bfloat16_rn(v);
        size_t o = (size_t)(c0 + rr) * DD + r0 + xx;
        th[o] = h;
        tl[o] = __float2bfloat16_rn(v - __bfloat162float(h));
    }
}
__global__ void __launch_bounds__(256) trans_split(
    const float* __restrict__ W, __nv_bfloat16* __restrict__ th,
    __nv_bfloat16* __restrict__ tl)
{
    __shared__ float t[32][33];
    int r0 = blockIdx.y * 32, c0 = blockIdx.x * 32;
    int xx = threadIdx.x & 31, yy = threadIdx.x >> 5;
    for (int rr = yy; rr < 32; rr += 8)
        t[rr][xx] = W[(size_t)(r0 + rr) * DD + c0 + xx];
    __syncthreads();
    for (int rr = yy; rr < 32; rr += 8) {
        float v = t[xx][rr];
        __nv_bfloat16 h = __float2bfloat16_rn(v);
        size_t o = (size_t)(c0 + rr) * DD + r0 + xx;
        th[o] = h;
        tl[o] = __float2bfloat16_rn(v - __bfloat162float(h));
    }
}

// W_clock [K=2048][16] -> padded transpose rows [128][2048] at fused slot 5
__global__ void __launch_bounds__(256) build_wclk(const float* __restrict__ Wcl)
{
    int idx = blockIdx.x * 256 + threadIdx.x;   // over 128*2048
    int r = idx >> 11, k = idx & 2047;
    float v = (r < HH) ? Wcl[k * HH + r] : 0.f;
    __nv_bfloat16 h = __float2bfloat16_rn(v);
    size_t o = (size_t)5 * DD * DD + (size_t)r * DD + k;
    g_wth[o] = h;
    g_wtl[o] = __float2bfloat16_rn(v - __bfloat162float(h));
}

// ==================== HMMA split-bf16 GEMM: C = A @ B^T =====================
// A [M][K] bf16 hi/lo row-major, B [N][K] bf16 hi/lo. CTA 128x128, BK=64,
// 512 threads (16 warps: wm 0..3 x wn 0..3, warp tile 32x32), 3-stage
// cp.async pipeline identical to the proven 256-thread version. 144B rows.
// fused != 0: logical bx = blockIdx.x + bx0 in [0,81): j = bx>>4 selects
// output (0:q 1:k 2:v-split 3:p 4:g 5:clock+logclock).
#define GM_STG 73728
#define GM_SMEM (3*GM_STG)   // 221184 bytes

__global__ void __launch_bounds__(512, 1) tgemm_mma(
    const __nv_bfloat16* __restrict__ Ah, const __nv_bfloat16* __restrict__ Al,
    const __nv_bfloat16* __restrict__ Bh, const __nv_bfloat16* __restrict__ Bl,
    float* __restrict__ C, int fused, int bx0)
{
    extern __shared__ char sm[];
    const uint32_t sb = smem_u32(sm);
    const int tid = threadIdx.x, wid = tid >> 5, lane = tid & 31;
    const int wm = wid >> 2, wn = wid & 3;   // 4 x 4 warp grid, 32x32 tiles
    const int bx = blockIdx.x + bx0, by = blockIdx.y;

    float acc[2][4][4];
#pragma unroll
    for (int i = 0; i < 2; i++)
#pragma unroll
        for (int j = 0; j < 4; j++)
#pragma unroll
            for (int r = 0; r < 4; r++) acc[i][j][r] = 0.f;

    auto load_stage = [&](int st, int kc) {
        uint32_t base = sb + st * GM_STG;
#pragma unroll
        for (int i = 0; i < 2; i++) {
            int u = tid + i * 512, row = u >> 3, c8 = u & 7;   // 1024 = 128x8
            uint32_t off = base + row * 144 + c8 * 16;
            size_t ga = (size_t)(by * 128 + row) * DD + kc * 64 + c8 * 8;
            size_t gb = (size_t)(bx * 128 + row) * DD + kc * 64 + c8 * 8;
            CP16(off,         Ah + ga);
            CP16(off + 18432, Al + ga);
            CP16(off + 36864, Bh + gb);
            CP16(off + 55296, Bl + gb);
        }
    };
    load_stage(0, 0); CP_COMMIT();
    load_stage(1, 1); CP_COMMIT();

    for (int kc = 0; kc < 32; kc++) {
        int st = kc % 3;
        if (kc < 31) { CP_WAIT1(); } else { CP_WAIT0(); }
        __syncthreads();
        if (kc + 2 < 32) load_stage((kc + 2) % 3, kc + 2);
        CP_COMMIT();
        uint32_t base = sb + st * GM_STG;
#pragma unroll
        for (int ks = 0; ks < 4; ks++) {
            uint32_t aH[2][4], aL[2][4];
#pragma unroll
            for (int mt = 0; mt < 2; mt++) {
                uint32_t aa = base + (wm * 32 + mt * 16 + (lane & 15)) * 144
                            + ks * 32 + (lane >> 4) * 16;
                ldsm4(aH[mt], aa);
                ldsm4(aL[mt], aa + 18432);
            }
#pragma unroll
            for (int nf2 = 0; nf2 < 2; nf2++) {
                uint32_t bH[4], bL[4];
                uint32_t ba = base + 36864
                            + (wn * 32 + nf2 * 16 + (lane & 7) + ((lane >> 4) << 3)) * 144
                            + ks * 32 + ((lane >> 3) & 1) * 16;
                ldsm4(bH, ba);
                ldsm4(bL, ba + 18432);
#pragma unroll
                for (int mt = 0; mt < 2; mt++) {
                    mma_bf(acc[mt][2 * nf2],     aH[mt], bH[0], bH[1]);
                    mma_bf(acc[mt][2 * nf2 + 1], aH[mt], bH[2], bH[3]);
                    mma_bf(acc[mt][2 * nf2],     aH[mt], bL[0], bL[1]);
                    mma_bf(acc[mt][2 * nf2 + 1], aH[mt], bL[2], bL[3]);
                    mma_bf(acc[mt][2 * nf2],     aL[mt], bH[0], bH[1]);
                    mma_bf(acc[mt][2 * nf2 + 1], aL[mt], bH[2], bH[3]);
                }
            }
        }
    }

    if (!fused) {
#pragma unroll
        for (int mt = 0; mt < 2; mt++)
#pragma unroll
            for (int nf = 0; nf < 4; nf++) {
                int row = by * 128 + wm * 32 + mt * 16 + (lane >> 2);
                int col = bx * 128 + wn * 32 + nf * 8 + (lane & 3) * 2;
                *(float2*)(C + (size_t)row * DD + col) =
                    make_float2(acc[mt][nf][0], acc[mt][nf][1]);
                *(float2*)(C + (size_t)(row + 8) * DD + col) =
                    make_float2(acc[mt][nf][2], acc[mt][nf][3]);
            }
    } else {
        int j = bx >> 4;
        int colb = (bx & 15) * 128;
        if (j == 5) {
            // clock slice: only cols < 16 valid (wn==0, nf<2)
            if (wn == 0) {
#pragma unroll
                for (int mt = 0; mt < 2; mt++)
#pragma unroll
                    for (int nf = 0; nf < 2; nf++) {
                        int row = by * 128 + wm * 32 + mt * 16 + (lane >> 2);
                        int col = nf * 8 + (lane & 3) * 2;
                        float c0 = softplus_f(acc[mt][nf][0]) + 1e-6f;
                        float c1 = softplus_f(acc[mt][nf][1]) + 1e-6f;
                        float c2 = softplus_f(acc[mt][nf][2]) + 1e-6f;
                        float c3 = softplus_f(acc[mt][nf][3]) + 1e-6f;
                        g_clockbuf[row * HH + col]           = c0;
                        g_clockbuf[row * HH + col + 1]       = c1;
                        g_clockbuf[(row + 8) * HH + col]     = c2;
                        g_clockbuf[(row + 8) * HH + col + 1] = c3;
                        g_logclock[row * HH + col]           = __logf(c0);
                        g_logclock[row * HH + col + 1]       = __logf(c1);
                        g_logclock[(row + 8) * HH + col]     = __logf(c2);
                        g_logclock[(row + 8) * HH + col + 1] = __logf(c3);
                    }
            }
        } else if (j == 2) {
#pragma unroll
            for (int mt = 0; mt < 2; mt++)
#pragma unroll
                for (int nf = 0; nf < 4; nf++) {
                    int row = by * 128 + wm * 32 + mt * 16 + (lane >> 2);
                    int col = colb + wn * 32 + nf * 8 + (lane & 3) * 2;
                    uint32_t hi, lo;
                    packsplit(acc[mt][nf][0], acc[mt][nf][1], hi, lo);
                    *(uint32_t*)(g_vh + (size_t)row * DD + col) = hi;
                    *(uint32_t*)(g_vl + (size_t)row * DD + col) = lo;
                    packsplit(acc[mt][nf][2], acc[mt][nf][3], hi, lo);
                    *(uint32_t*)(g_vh + (size_t)(row + 8) * DD + col) = hi;
                    *(uint32_t*)(g_vl + (size_t)(row + 8) * DD + col) = lo;
                }
        } else {
            float* Cj = (j == 0) ? g_q : (j == 1) ? g_k : (j == 3) ? g_p : g_g;
#pragma unroll
            for (int mt = 0; mt < 2; mt++)
#pragma unroll
                for (int nf = 0; nf < 4; nf++) {
                    int row = by * 128 + wm * 32 + mt * 16 + (lane >> 2);
                    int col = colb + wn * 32 + nf * 8 + (lane & 3) * 2;
                    *(float2*)(Cj + (size_t)row * DD + col) =
                        make_float2(acc[mt][nf][0], acc[mt][nf][1]);
                    *(float2*)(Cj + (size_t)(row + 8) * DD + col) =
                        make_float2(acc[mt][nf][2], acc[mt][nf][3]);
                }
        }
    }
}

// ---------------- scan phase 1: per-chunk partials ---------------------------
__global__ void __launch_bounds__(128) scan_phase1()
{
    int c = blockIdx.x, bh = blockIdx.y, d = threadIdx.x;
    int b = bh >> 4, h = bh & 15;
    float pmax = -INFINITY, psum = 0.f, gsum = 0.f, csum = 0.f;
    for (int t = c * CL; t < (c + 1) * CL; t++) {
        int n = b * TT + t;
        float ck = g_clockbuf[n * HH + h];
        float lck = g_logclock[n * HH + h];
        size_t idx = (size_t)n * DD + h * DHD + d;
        float pv = g_p[idx] + lck;
        if (pv > pmax) { psum = psum * __expf(pmax - pv) + 1.f; pmax = pv; }
        else psum += __expf(pv - pmax);
        gsum += -softplus_fast(g_g[idx]) * ck;
        csum += ck;
    }
    int o = (bh * NC + c) * DHD + d;
    g_part_pm[o] = pmax; g_part_ps[o] = psum;
    g_part_gs[o] = gsum; g_part_cs[o] = csum;
}

// ------- scan phase 3 (with fused phase-2 prefix): cumsums + RoPE + split ----
__global__ void __launch_bounds__(128) scan_phase3()
{
    int c = blockIdx.x, bh = blockIdx.y, d = threadIdx.x;
    int b = bh >> 4, h = bh & 15;
    float gmax = -INFINITY;
#pragma unroll 4
    for (int c2 = 0; c2 < NC; c2++)
        gmax = fmaxf(gmax, g_part_pm[(bh * NC + c2) * DHD + d]);
    float pcs = 0.f, gcs = 0.f, ccs = 0.f;
    for (int c2 = 0; c2 < c; c2++) {
        int o2 = (bh * NC + c2) * DHD + d;
        pcs += g_part_ps[o2] * __expf(g_part_pm[o2] - gmax);
        gcs += g_part_gs[o2];
        ccs += g_part_cs[o2];
    }
    int fi = d & 63;
    float invf = expf(-(float)fi * (logf(10000.f) / 64.f));
    float sgn = (d & 1) ? 1.f : -1.f;
    const float scale = rsqrtf(384.f);
    float cs_, sn_, cd, sd;
    sincosf((float)(c * CL) * invf, &sn_, &cs_);
    sincosf(invf, &sd, &cd);
    for (int t = c * CL; t < (c + 1) * CL; t++) {
        int n = b * TT + t;
        float ck = g_clockbuf[n * HH + h];
        float lck = g_logclock[n * HH + h];
        size_t idx = (size_t)n * DD + h * DHD + d;
        float pe = __expf(g_p[idx] + lck - gmax);
        pcs += pe;
        gcs += -softplus_fast(g_g[idx]) * ck;
        float gcp = __expf(fminf(fmaxf(gcs, -50.f), 40.f));
        ccs += ck;
        float qv = g_q[idx], kv = g_k[idx];
        float qp = __shfl_xor_sync(0xffffffffu, qv, 1);
        float kp = __shfl_xor_sync(0xffffffffu, kv, 1);
        float qr = qv * cs_ + sgn * qp * sn_;
        float kr = kv * cs_ + sgn * kp * sn_;
        size_t co = ((size_t)n * HH + h) * DC + d;
        float qs[3], kss[3];
        qs[0] = scale * qr / (pcs + 1e-8f);
        qs[1] = scale * qr * gcp;
        qs[2] = scale * qr / ccs;
        kss[0] = kr * pe;
        kss[1] = kr / (gcp + 1e-8f);
        kss[2] = kr * ck;
#pragma unroll
        for (int j = 0; j < 3; j++) {
            __nv_bfloat16 hq = __float2bfloat16_rn(qs[j]);
            g_qch[co + j * DHD] = hq;
            g_qcl[co + j * DHD] = __float2bfloat16_rn(qs[j] - __bfloat162float(hq));
            __nv_bfloat16 hk = __float2bfloat16_rn(kss[j]);
            g_kch[co + j * DHD] = hk;
            g_kcl[co + j * DHD] = __float2bfloat16_rn(kss[j] - __bfloat162float(hk));
        }
        float nc_ = cs_ * cd - sn_ * sd;
        float ns_ = sn_ * cd + cs_ * sd;
        cs_ = nc_; sn_ = ns_;
    }
}

// ==================== flash attention v4: HMMA + cp.async pipeline ===========
// 8 warps x 16 q-rows = 128 queries per CTA; full 2048-key scan.
#define AT_STG 73728
#define AT_VOFF (2*AT_STG)
#define AT_V 34816
#define AT_SMEM (2*AT_STG + 2*AT_V)   // 217088

__global__ void __launch_bounds__(256, 1) att3()
{
    extern __shared__ char sm[];
    const uint32_t sb = smem_u32(sm);
    const int tid = threadIdx.x, w = tid >> 5, lane = tid & 31;
    const int tq0 = blockIdx.x * 128;
    const int bh = blockIdx.y, b = bh >> 4, h = bh & 15;

    float acco[16][4];
    float m[2] = { -INFINITY, -INFINITY }, l[2] = { 0.f, 0.f };
#pragma unroll
    for (int i = 0; i < 16; i++)
#pragma unroll
        for (int r = 0; r < 4; r++) acco[i][r] = 0.f;

    auto issue_qk = [&](int buf, int s0, int kc) {
        uint32_t base = sb + buf * AT_STG;
#pragma unroll
        for (int i = 0; i < 4; i++) {
            int u = tid + i * 256, row = u >> 3, c8 = u & 7;
            uint32_t off = base + row * 144 + c8 * 16;
            size_t qg = ((size_t)(b * TT + tq0 + row) * HH + h) * DC + kc * 64 + c8 * 8;
            size_t kg = ((size_t)(b * TT + s0 + row) * HH + h) * DC + kc * 64 + c8 * 8;
            CP16(off,         g_qch + qg);
            CP16(off + 18432, g_qcl + qg);
            CP16(off + 36864, g_kch + kg);
            CP16(off + 55296, g_kcl + kg);
        }
    };

    for (int s0 = 0; s0 < TT; s0 += 128) {
#pragma unroll
        for (int i = 0; i < 8; i++) {
            int u = tid + i * 256, row = u >> 4, c16 = u & 15;
            uint32_t off = sb + AT_VOFF + row * 272 + c16 * 16;
            size_t vg = (size_t)(b * TT + s0 + row) * DD + h * 128 + c16 * 8;
            CP16(off,        g_vh + vg);
            CP16(off + AT_V, g_vl + vg);
        }
        issue_qk(0, s0, 0); CP_COMMIT();
        issue_qk(1, s0, 1); CP_COMMIT();

        float accs[16][4];
#pragma unroll
        for (int i = 0; i < 16; i++)
#pragma unroll
            for (int r = 0; r < 4; r++) accs[i][r] = 0.f;

        for (int kc = 0; kc < 6; kc++) {
            if (kc < 5) { CP_WAIT1(); } else { CP_WAIT0(); }
            __syncthreads();
            uint32_t base = sb + (kc & 1) * AT_STG;
#pragma unroll
            for (int ks = 0; ks < 4; ks++) {
                uint32_t aH[4], aL[4];
                uint32_t aa = base + (w * 16 + (lane & 15)) * 144 + ks * 32 + (lane >> 4) * 16;
                ldsm4(aH, aa);
                ldsm4(aL, aa + 18432);
#pragma unroll
                for (int nf2 = 0; nf2 < 8; nf2++) {
                    uint32_t bH[4], bL[4];
                    uint32_t ba = base + 36864
                                + (nf2 * 16 + (lane & 7) + ((lane >> 4) << 3)) * 144
                                + ks * 32 + ((lane >> 3) & 1) * 16;
                    ldsm4(bH, ba);
                    ldsm4(bL, ba + 18432);
                    mma_bf(accs[2 * nf2],     aH, bH[0], bH[1]);
                    mma_bf(accs[2 * nf2 + 1], aH, bH[2], bH[3]);
                    mma_bf(accs[2 * nf2],     aH, bL[0], bL[1]);
                    mma_bf(accs[2 * nf2 + 1], aH, bL[2], bL[3]);
                    mma_bf(accs[2 * nf2],     aL, bH[0], bH[1]);
                    mma_bf(accs[2 * nf2 + 1], aL, bH[2], bH[3]);
                }
            }
            __syncthreads();
            if (kc + 2 < 6) { issue_qk(kc & 1, s0, kc + 2); CP_COMMIT(); }
        }

#pragma unroll
        for (int hf = 0; hf < 2; hf++) {
            float mt = -INFINITY;
#pragma unroll
            for (int nf = 0; nf < 16; nf++)
                mt = fmaxf(mt, fmaxf(accs[nf][2 * hf], accs[nf][2 * hf + 1]));
            mt = fmaxf(mt, __shfl_xor_sync(0xffffffffu, mt, 1));
            mt = fmaxf(mt, __shfl_xor_sync(0xffffffffu, mt, 2));
            float mn = fmaxf(m[hf], mt);
            float corr = __expf(m[hf] - mn);
            float ls = 0.f;
#pragma unroll
            for (int nf = 0; nf < 16; nf++) {
                float p0 = __expf(accs[nf][2 * hf] - mn);
                float p1 = __expf(accs[nf][2 * hf + 1] - mn);
                accs[nf][2 * hf] = p0; accs[nf][2 * hf + 1] = p1;
                ls += p0 + p1;
            }
            ls += __shfl_xor_sync(0xffffffffu, ls, 1);
            ls += __shfl_xor_sync(0xffffffffu, ls, 2);
            l[hf] = l[hf] * corr + ls;
            m[hf] = mn;
#pragma unroll
            for (int nf = 0; nf < 16; nf++) {
                acco[nf][2 * hf]     *= corr;
                acco[nf][2 * hf + 1] *= corr;
            }
        }

        uint32_t ph[8][4], pl[8][4];
#pragma unroll
        for (int kf = 0; kf < 8; kf++) {
            packsplit(accs[2 * kf][0],     accs[2 * kf][1],     ph[kf][0], pl[kf][0]);
            packsplit(accs[2 * kf][2],     accs[2 * kf][3],     ph[kf][1], pl[kf][1]);
            packsplit(accs[2 * kf + 1][0], accs[2 * kf + 1][1], ph[kf][2], pl[kf][2]);
            packsplit(accs[2 * kf + 1][2], accs[2 * kf + 1][3], ph[kf][3], pl[kf][3]);
        }

#pragma unroll
        for (int nf2 = 0; nf2 < 8; nf2++) {
#pragma unroll
            for (int kf = 0; kf < 8; kf++) {
                uint32_t vH[4], vL[4];
                uint32_t va = sb + AT_VOFF
                            + (kf * 16 + (lane & 7) + (((lane >> 3) & 1) << 3)) * 272
                            + (nf2 * 16 + ((lane >> 4) << 3)) * 2;
                ldsm4t(vH, va);
                ldsm4t(vL, va + AT_V);
                mma_bf(acco[2 * nf2],     ph[kf], vH[0], vH[1]);
                mma_bf(acco[2 * nf2 + 1], ph[kf], vH[2], vH[3]);
                mma_bf(acco[2 * nf2],     ph[kf], vL[0], vL[1]);
                mma_bf(acco[2 * nf2 + 1], ph[kf], vL[2], vL[3]);
                mma_bf(acco[2 * nf2],     pl[kf], vH[0], vH[1]);
                mma_bf(acco[2 * nf2 + 1], pl[kf], vH[2], vH[3]);
            }
        }
        __syncthreads();
    }

    // ---- epilogue: write O as bf16 hi/lo (feeds final GEMM directly) ----
    float i0 = 1.f / l[0], i1 = 1.f / l[1];
    int r0 = b * TT + tq0 + w * 16 + (lane >> 2);
#pragma unroll
    for (int nf = 0; nf < 16; nf++) {
        int col = h * 128 + nf * 8 + 2 * (lane & 3);
        size_t o0 = (size_t)r0 * DD + col;
        size_t o1 = o0 + (size_t)8 * DD;
        uint32_t hi, lo;
        packsplit(acco[nf][0] * i0, acco[nf][1] * i0, hi, lo);
        *(uint32_t*)(g_ah + o0) = hi; *(uint32_t*)(g_al + o0) = lo;
        packsplit(acco[nf][2] * i1, acco[nf][3] * i1, hi, lo);
        *(uint32_t*)(g_ah + o1) = hi; *(uint32_t*)(g_al + o1) = lo;
    }
}

// ---------------- launch ----------------------------------------------------
extern "C" void kernel_launch(void* const* d_in, const int* in_sizes, int n_in,
                              void* d_out, int out_size)
{
    const float* x   = (const float*)d_in[0];
    const float* Wq  = (const float*)d_in[1];
    const float* Wk  = (const float*)d_in[2];
    const float* Wv  = (const float*)d_in[3];
    const float* Wg  = (const float*)d_in[4];
    const float* Wp  = (const float*)d_in[5];
    const float* Wcl = (const float*)d_in[6];
    const float* Wc  = (const float*)d_in[7];
    float* out = (float*)d_out;

    __nv_bfloat16 *pxh, *pxl, *pah, *pal, *pwth, *pwtl, *pwch, *pwcl;
    cudaGetSymbolAddress((void**)&pxh, g_xh);
    cudaGetSymbolAddress((void**)&pxl, g_xl);
    cudaGetSymbolAddress((void**)&pah, g_ah);
    cudaGetSymbolAddress((void**)&pal, g_al);
    cudaGetSymbolAddress((void**)&pwth, g_wth);
    cudaGetSymbolAddress((void**)&pwtl, g_wtl);
    cudaGetSymbolAddress((void**)&pwch, g_wch);
    cudaGetSymbolAddress((void**)&pwcl, g_wcl);

    cudaFuncSetAttribute(tgemm_mma, cudaFuncAttributeMaxDynamicSharedMemorySize, GM_SMEM);
    cudaFuncSetAttribute(att3, cudaFuncAttributeMaxDynamicSharedMemorySize, AT_SMEM);

    // launches 1-3: prep. Launches #4/#5 are the two fused-GEMM halves so the
    // profiler lands on tgemm_mma.
    conv_split<<<(NROWS * DD / 4 + 255) / 256, 256>>>(
        (const float4*)x, (uint2*)pxh, (uint2*)pxl, NROWS * DD / 4);          // 1
    build_wclk<<<(128 * DD) / 256, 256>>>(Wcl);                               // 2
    W5 ws; ws.w[0] = Wq; ws.w[1] = Wk; ws.w[2] = Wv; ws.w[3] = Wp; ws.w[4] = Wg;
    trans_split5<<<dim3(DD / 32, DD / 32, 5), 256>>>(ws, pwth, pwtl);         // 3

    // fused projection GEMM: 5 weights + clock head (N = 10368)
    tgemm_mma<<<dim3(41, NROWS / 128), 512, GM_SMEM>>>(
        pxh, pxl, pwth, pwtl, (float*)nullptr, 1, 0);                         // 4
    tgemm_mma<<<dim3(40, NROWS / 128), 512, GM_SMEM>>>(
        pxh, pxl, pwth, pwtl, (float*)nullptr, 1, 41);                        // 5

    trans_split<<<dim3(DD / 32, DD / 32), 256>>>(Wc, pwch, pwcl);             // 6

    scan_phase1<<<dim3(NC, BB * HH), 128>>>();
    scan_phase3<<<dim3(NC, BB * HH), 128>>>();   // phase 2 fused in

    att3<<<dim3(TT / 128, BB * HH), 256, AT_SMEM>>>();

    tgemm_mma<<<dim3(DD / 128, NROWS / 128), 512, GM_SMEM>>>(
        pah, pal, pwch, pwcl, out, 0, 0);
}

// round 15
// speedup vs baseline: 1.0435x; 1.0435x over previous
#include <cuda_runtime.h>
#include <cuda_bf16.h>
#include <math.h>
#include <stdint.h>

#define BB 2
#define TT 2048
#define DD 2048
#define HH 16
#define DHD 128
#define DC 384
#define NROWS (BB*TT)        // 4096
#define NC 32
#define CL (TT/NC)           // 64

// ---------------- scratch (device globals: no runtime allocation allowed) ----
__device__ float g_q[NROWS*DD];
__device__ float g_k[NROWS*DD];
__device__ float g_p[NROWS*DD];
__device__ float g_g[NROWS*DD];
__device__ float g_clockbuf[NROWS*HH];
__device__ float g_logclock[NROWS*HH];
__device__ float g_part_pm[BB*HH*NC*DHD];
__device__ float g_part_ps[BB*HH*NC*DHD];
__device__ float g_part_gs[BB*HH*NC*DHD];
__device__ float g_part_cs[BB*HH*NC*DHD];

// bf16 split operands
__device__ __align__(16) __nv_bfloat16 g_xh[(size_t)NROWS*DD];
__device__ __align__(16) __nv_bfloat16 g_xl[(size_t)NROWS*DD];
__device__ __align__(16) __nv_bfloat16 g_ah[(size_t)NROWS*DD];   // attention out hi
__device__ __align__(16) __nv_bfloat16 g_al[(size_t)NROWS*DD];   // attention out lo
__device__ __align__(16) __nv_bfloat16 g_vh[(size_t)NROWS*DD];
__device__ __align__(16) __nv_bfloat16 g_vl[(size_t)NROWS*DD];
// fused projection B: [Wq Wk Wv Wp Wg | W_clock^T padded to 128 rows]
#define FUSED_ROWS (5*DD + 128)      // 10368
__device__ __align__(16) __nv_bfloat16 g_wth[(size_t)FUSED_ROWS*DD];
__device__ __align__(16) __nv_bfloat16 g_wtl[(size_t)FUSED_ROWS*DD];
__device__ __align__(16) __nv_bfloat16 g_wch[(size_t)DD*DD];     // Wc^T hi
__device__ __align__(16) __nv_bfloat16 g_wcl[(size_t)DD*DD];     // Wc^T lo
__device__ __align__(16) __nv_bfloat16 g_qch[(size_t)NROWS*HH*DC];
__device__ __align__(16) __nv_bfloat16 g_qcl[(size_t)NROWS*HH*DC];
__device__ __align__(16) __nv_bfloat16 g_kch[(size_t)NROWS*HH*DC];
__device__ __align__(16) __nv_bfloat16 g_kcl[(size_t)NROWS*HH*DC];

__device__ __forceinline__ float softplus_f(float x) {
    return fmaxf(x, 0.f) + log1pf(expf(-fabsf(x)));
}
__device__ __forceinline__ float softplus_fast(float x) {
    return fmaxf(x, 0.f) + __logf(1.f + __expf(-fabsf(x)));
}

// ==================== warp-mma helpers (family-common PTX) ===================
__device__ __forceinline__ uint32_t smem_u32(const void* p) {
    uint32_t a;
    asm("{ .reg .u64 t; cvta.to.shared.u64 t, %1; cvt.u32.u64 %0, t; }"
        : "=r"(a) : "l"(p));
    return a;
}
__device__ __forceinline__ void ldsm4(uint32_t r[4], uint32_t a) {
    asm volatile("ldmatrix.sync.aligned.m8n8.x4.shared.b16 {%0,%1,%2,%3}, [%4];"
        : "=r"(r[0]), "=r"(r[1]), "=r"(r[2]), "=r"(r[3]) : "r"(a));
}
__device__ __forceinline__ void ldsm4t(uint32_t r[4], uint32_t a) {
    asm volatile("ldmatrix.sync.aligned.m8n8.x4.trans.shared.b16 {%0,%1,%2,%3}, [%4];"
        : "=r"(r[0]), "=r"(r[1]), "=r"(r[2]), "=r"(r[3]) : "r"(a));
}
__device__ __forceinline__ void mma_bf(float c[4], const uint32_t a[4],
                                       uint32_t b0, uint32_t b1) {
    asm volatile(
        "mma.sync.aligned.m16n8k16.row.col.f32.bf16.bf16.f32 "
        "{%0,%1,%2,%3}, {%4,%5,%6,%7}, {%8,%9}, {%0,%1,%2,%3};"
        : "+f"(c[0]), "+f"(c[1]), "+f"(c[2]), "+f"(c[3])
        : "r"(a[0]), "r"(a[1]), "r"(a[2]), "r"(a[3]), "r"(b0), "r"(b1));
}
__device__ __forceinline__ void packsplit(float x, float y, uint32_t& hi, uint32_t& lo) {
    __nv_bfloat16 hx = __float2bfloat16_rn(x), hy = __float2bfloat16_rn(y);
    __nv_bfloat162 h2; h2.x = hx; h2.y = hy;
    __nv_bfloat162 l2;
    l2.x = __float2bfloat16_rn(x - __bfloat162float(hx));
    l2.y = __float2bfloat16_rn(y - __bfloat162float(hy));
    hi = *(uint32_t*)&h2; lo = *(uint32_t*)&l2;
}
#define CP16(dst, src) asm volatile("cp.async.cg.shared.global [%0], [%1], 16;" :: "r"(dst), "l"(src))
#define CP_COMMIT() asm volatile("cp.async.commit_group;" ::: "memory")
#define CP_WAIT0()  asm volatile("cp.async.wait_group 0;" ::: "memory")
#define CP_WAIT1()  asm volatile("cp.async.wait_group 1;" ::: "memory")

// ==================== split conversion kernels ==============================
__global__ void __launch_bounds__(256) conv_split(
    const float4* __restrict__ src, uint2* __restrict__ hi, uint2* __restrict__ lo, int n4)
{
    int i = blockIdx.x * 256 + threadIdx.x;
    if (i >= n4) return;
    float4 v = src[i];
    __nv_bfloat16 h0 = __float2bfloat16_rn(v.x), h1 = __float2bfloat16_rn(v.y);
    __nv_bfloat16 h2 = __float2bfloat16_rn(v.z), h3 = __float2bfloat16_rn(v.w);
    __nv_bfloat16 l0 = __float2bfloat16_rn(v.x - __bfloat162float(h0));
    __nv_bfloat16 l1 = __float2bfloat16_rn(v.y - __bfloat162float(h1));
    __nv_bfloat16 l2 = __float2bfloat16_rn(v.z - __bfloat162float(h2));
    __nv_bfloat16 l3 = __float2bfloat16_rn(v.w - __bfloat162float(h3));
    hi[i] = make_uint2((uint32_t)__bfloat16_as_ushort(h0) | ((uint32_t)__bfloat16_as_ushort(h1) << 16),
                       (uint32_t)__bfloat16_as_ushort(h2) | ((uint32_t)__bfloat16_as_ushort(h3) << 16));
    lo[i] = make_uint2((uint32_t)__bfloat16_as_ushort(l0) | ((uint32_t)__bfloat16_as_ushort(l1) << 16),
                       (uint32_t)__bfloat16_as_ushort(l2) | ((uint32_t)__bfloat16_as_ushort(l3) << 16));
}

// W[K][N] fp32 -> WT[N][K] bf16 hi/lo, batched over 6 weights via blockIdx.z
// j<5 -> fused projection slots; j==5 -> Wc buffers.
struct W6 { const float* w[6]; };
__global__ void __launch_bounds__(256) trans_split6(
    W6 ws, __nv_bfloat16* __restrict__ th5, __nv_bfloat16* __restrict__ tl5,
    __nv_bfloat16* __restrict__ thc, __nv_bfloat16* __restrict__ tlc)
{
    __shared__ float t[32][33];
    int j = blockIdx.z;
    const float* W = ws.w[j];
    __nv_bfloat16* th = (j < 5) ? th5 + (size_t)j * DD * DD : thc;
    __nv_bfloat16* tl = (j < 5) ? tl5 + (size_t)j * DD * DD : tlc;
    int r0 = blockIdx.y * 32, c0 = blockIdx.x * 32;
    int xx = threadIdx.x & 31, yy = threadIdx.x >> 5;
    for (int rr = yy; rr < 32; rr += 8)
        t[rr][xx] = W[(size_t)(r0 + rr) * DD + c0 + xx];
    __syncthreads();
    for (int rr = yy; rr < 32; rr += 8) {
        float v = t[xx][rr];
        __nv_bfloat16 h = __float2bfloat16_rn(v);
        size_t o = (size_t)(c0 + rr) * DD + r0 + xx;
        th[o] = h;
        tl[o] = __float2bfloat16_rn(v - __bfloat162float(h));
    }
}

// W_clock [K=2048][16] -> padded transpose rows [128][2048] at fused slot 5
__global__ void __launch_bounds__(256) build_wclk(const float* __restrict__ Wcl)
{
    int idx = blockIdx.x * 256 + threadIdx.x;   // over 128*2048
    int r = idx >> 11, k = idx & 2047;
    float v = (r < HH) ? Wcl[k * HH + r] : 0.f;
    __nv_bfloat16 h = __float2bfloat16_rn(v);
    size_t o = (size_t)5 * DD * DD + (size_t)r * DD + k;
    g_wth[o] = h;
    g_wtl[o] = __float2bfloat16_rn(v - __bfloat162float(h));
}

// ==================== HMMA split-bf16 GEMM: C = A @ B^T =====================
// Proven r11 config: CTA 128x128, 256 threads (8 warps, 2x4 grid, 64x32 warp
// tiles), BK=64, 3-stage cp.async pipeline, 144B rows. NEW: explicit ks-level
// register double-buffering of ldmatrix fragments (same values, same
// per-accumulator MMA order -> bitwise identical results).
// fused != 0: logical bx = blockIdx.x + bx0 in [0,81): j = bx>>4 selects
// output (0:q 1:k 2:v-split 3:p 4:g 5:clock+logclock).
#define GM_STG 73728
#define GM_SMEM (3*GM_STG)   // 221184 bytes

__global__ void __launch_bounds__(256, 1) tgemm_mma(
    const __nv_bfloat16* __restrict__ Ah, const __nv_bfloat16* __restrict__ Al,
    const __nv_bfloat16* __restrict__ Bh, const __nv_bfloat16* __restrict__ Bl,
    float* __restrict__ C, int fused, int bx0)
{
    extern __shared__ char sm[];
    const uint32_t sb = smem_u32(sm);
    const int tid = threadIdx.x, wid = tid >> 5, lane = tid & 31;
    const int wm = wid >> 2, wn = wid & 3;
    const int bx = blockIdx.x + bx0, by = blockIdx.y;

    float acc[4][4][4];
#pragma unroll
    for (int i = 0; i < 4; i++)
#pragma unroll
        for (int j = 0; j < 4; j++)
#pragma unroll
            for (int r = 0; r < 4; r++) acc[i][j][r] = 0.f;

    auto load_stage = [&](int st, int kc) {
        uint32_t base = sb + st * GM_STG;
#pragma unroll
        for (int i = 0; i < 4; i++) {
            int u = tid + i * 256, row = u >> 3, c8 = u & 7;
            uint32_t off = base + row * 144 + c8 * 16;
            size_t ga = (size_t)(by * 128 + row) * DD + kc * 64 + c8 * 8;
            size_t gb = (size_t)(bx * 128 + row) * DD + kc * 64 + c8 * 8;
            CP16(off,         Ah + ga);
            CP16(off + 18432, Al + ga);
            CP16(off + 36864, Bh + gb);
            CP16(off + 55296, Bl + gb);
        }
    };
    load_stage(0, 0); CP_COMMIT();
    load_stage(1, 1); CP_COMMIT();

    uint32_t aH[2][4][4], aL[2][4][4], bH[2][2][4], bL[2][2][4];

    for (int kc = 0; kc < 32; kc++) {
        int st = kc % 3;
        if (kc < 31) { CP_WAIT1(); } else { CP_WAIT0(); }
        __syncthreads();
        if (kc + 2 < 32) { load_stage((kc + 2) % 3, kc + 2); CP_COMMIT(); }
        uint32_t base = sb + st * GM_STG;

        // prime fragments for ks = 0 into slot 0
#pragma unroll
        for (int mt = 0; mt < 4; mt++) {
            uint32_t aa = base + (wm * 64 + mt * 16 + (lane & 15)) * 144
                        + (lane >> 4) * 16;
            ldsm4(aH[0][mt], aa);
            ldsm4(aL[0][mt], aa + 18432);
        }
#pragma unroll
        for (int nf2 = 0; nf2 < 2; nf2++) {
            uint32_t ba = base + 36864
                        + (wn * 32 + nf2 * 16 + (lane & 7) + ((lane >> 4) << 3)) * 144
                        + ((lane >> 3) & 1) * 16;
            ldsm4(bH[0][nf2], ba);
            ldsm4(bL[0][nf2], ba + 18432);
        }

#pragma unroll
        for (int ks = 0; ks < 4; ks++) {
            const int cur = ks & 1, nxt = cur ^ 1;
            if (ks < 3) {
                // prefetch ks+1 fragments while issuing ks MMAs below
#pragma unroll
                for (int mt = 0; mt < 4; mt++) {
                    uint32_t aa = base + (wm * 64 + mt * 16 + (lane & 15)) * 144
                                + (ks + 1) * 32 + (lane >> 4) * 16;
                    ldsm4(aH[nxt][mt], aa);
                    ldsm4(aL[nxt][mt], aa + 18432);
                }
#pragma unroll
                for (int nf2 = 0; nf2 < 2; nf2++) {
                    uint32_t ba = base + 36864
                                + (wn * 32 + nf2 * 16 + (lane & 7) + ((lane >> 4) << 3)) * 144
                                + (ks + 1) * 32 + ((lane >> 3) & 1) * 16;
                    ldsm4(bH[nxt][nf2], ba);
                    ldsm4(bL[nxt][nf2], ba + 18432);
                }
            }
#pragma unroll
            for (int nf2 = 0; nf2 < 2; nf2++) {
#pragma unroll
                for (int mt = 0; mt < 4; mt++) {
                    mma_bf(acc[mt][2 * nf2],     aH[cur][mt], bH[cur][nf2][0], bH[cur][nf2][1]);
                    mma_bf(acc[mt][2 * nf2 + 1], aH[cur][mt], bH[cur][nf2][2], bH[cur][nf2][3]);
                    mma_bf(acc[mt][2 * nf2],     aH[cur][mt], bL[cur][nf2][0], bL[cur][nf2][1]);
                    mma_bf(acc[mt][2 * nf2 + 1], aH[cur][mt], bL[cur][nf2][2], bL[cur][nf2][3]);
                    mma_bf(acc[mt][2 * nf2],     aL[cur][mt], bH[cur][nf2][0], bH[cur][nf2][1]);
                    mma_bf(acc[mt][2 * nf2 + 1], aL[cur][mt], bH[cur][nf2][2], bH[cur][nf2][3]);
                }
            }
        }
    }

    if (!fused) {
#pragma unroll
        for (int mt = 0; mt < 4; mt++)
#pragma unroll
            for (int nf = 0; nf < 4; nf++) {
                int row = by * 128 + wm * 64 + mt * 16 + (lane >> 2);
                int col = bx * 128 + wn * 32 + nf * 8 + (lane & 3) * 2;
                *(float2*)(C + (size_t)row * DD + col) =
                    make_float2(acc[mt][nf][0], acc[mt][nf][1]);
                *(float2*)(C + (size_t)(row + 8) * DD + col) =
                    make_float2(acc[mt][nf][2], acc[mt][nf][3]);
            }
    } else {
        int j = bx >> 4;
        int colb = (bx & 15) * 128;
        if (j == 5) {
            // clock slice: only cols < 16 valid (wn==0, nf<2)
            if (wn == 0) {
#pragma unroll
                for (int mt = 0; mt < 4; mt++)
#pragma unroll
                    for (int nf = 0; nf < 2; nf++) {
                        int row = by * 128 + wm * 64 + mt * 16 + (lane >> 2);
                        int col = nf * 8 + (lane & 3) * 2;
                        float c0 = softplus_f(acc[mt][nf][0]) + 1e-6f;
                        float c1 = softplus_f(acc[mt][nf][1]) + 1e-6f;
                        float c2 = softplus_f(acc[mt][nf][2]) + 1e-6f;
                        float c3 = softplus_f(acc[mt][nf][3]) + 1e-6f;
                        g_clockbuf[row * HH + col]           = c0;
                        g_clockbuf[row * HH + col + 1]       = c1;
                        g_clockbuf[(row + 8) * HH + col]     = c2;
                        g_clockbuf[(row + 8) * HH + col + 1] = c3;
                        g_logclock[row * HH + col]           = __logf(c0);
                        g_logclock[row * HH + col + 1]       = __logf(c1);
                        g_logclock[(row + 8) * HH + col]     = __logf(c2);
                        g_logclock[(row + 8) * HH + col + 1] = __logf(c3);
                    }
            }
        } else if (j == 2) {
#pragma unroll
            for (int mt = 0; mt < 4; mt++)
#pragma unroll
                for (int nf = 0; nf < 4; nf++) {
                    int row = by * 128 + wm * 64 + mt * 16 + (lane >> 2);
                    int col = colb + wn * 32 + nf * 8 + (lane & 3) * 2;
                    uint32_t hi, lo;
                    packsplit(acc[mt][nf][0], acc[mt][nf][1], hi, lo);
                    *(uint32_t*)(g_vh + (size_t)row * DD + col) = hi;
                    *(uint32_t*)(g_vl + (size_t)row * DD + col) = lo;
                    packsplit(acc[mt][nf][2], acc[mt][nf][3], hi, lo);
                    *(uint32_t*)(g_vh + (size_t)(row + 8) * DD + col) = hi;
                    *(uint32_t*)(g_vl + (size_t)(row + 8) * DD + col) = lo;
                }
        } else {
            float* Cj = (j == 0) ? g_q : (j == 1) ? g_k : (j == 3) ? g_p : g_g;
#pragma unroll
            for (int mt = 0; mt < 4; mt++)
#pragma unroll
                for (int nf = 0; nf < 4; nf++) {
                    int row = by * 128 + wm * 64 + mt * 16 + (lane >> 2);
                    int col = colb + wn * 32 + nf * 8 + (lane & 3) * 2;
                    *(float2*)(Cj + (size_t)row * DD + col) =
                        make_float2(acc[mt][nf][0], acc[mt][nf][1]);
                    *(float2*)(Cj + (size_t)(row + 8) * DD + col) =
                        make_float2(acc[mt][nf][2], acc[mt][nf][3]);
                }
        }
    }
}

// ---------------- scan phase 1: per-chunk partials ---------------------------
__global__ void __launch_bounds__(128) scan_phase1()
{
    int c = blockIdx.x, bh = blockIdx.y, d = threadIdx.x;
    int b = bh >> 4, h = bh & 15;
    float pmax = -INFINITY, psum = 0.f, gsum = 0.f, csum = 0.f;
    for (int t = c * CL; t < (c + 1) * CL; t++) {
        int n = b * TT + t;
        float ck = g_clockbuf[n * HH + h];
        float lck = g_logclock[n * HH + h];
        size_t idx = (size_t)n * DD + h * DHD + d;
        float pv = g_p[idx] + lck;
        if (pv > pmax) { psum = psum * __expf(pmax - pv) + 1.f; pmax = pv; }
        else psum += __expf(pv - pmax);
        gsum += -softplus_fast(g_g[idx]) * ck;
        csum += ck;
    }
    int o = (bh * NC + c) * DHD + d;
    g_part_pm[o] = pmax; g_part_ps[o] = psum;
    g_part_gs[o] = gsum; g_part_cs[o] = csum;
}

// ------- scan phase 3 (with fused phase-2 prefix): cumsums + RoPE + split ----
__global__ void __launch_bounds__(128) scan_phase3()
{
    int c = blockIdx.x, bh = blockIdx.y, d = threadIdx.x;
    int b = bh >> 4, h = bh & 15;
    float gmax = -INFINITY;
#pragma unroll 4
    for (int c2 = 0; c2 < NC; c2++)
        gmax = fmaxf(gmax, g_part_pm[(bh * NC + c2) * DHD + d]);
    float pcs = 0.f, gcs = 0.f, ccs = 0.f;
    for (int c2 = 0; c2 < c; c2++) {
        int o2 = (bh * NC + c2) * DHD + d;
        pcs += g_part_ps[o2] * __expf(g_part_pm[o2] - gmax);
        gcs += g_part_gs[o2];
        ccs += g_part_cs[o2];
    }
    int fi = d & 63;
    float invf = expf(-(float)fi * (logf(10000.f) / 64.f));
    float sgn = (d & 1) ? 1.f : -1.f;
    const float scale = rsqrtf(384.f);
    float cs_, sn_, cd, sd;
    sincosf((float)(c * CL) * invf, &sn_, &cs_);
    sincosf(invf, &sd, &cd);
    for (int t = c * CL; t < (c + 1) * CL; t++) {
        int n = b * TT + t;
        float ck = g_clockbuf[n * HH + h];
        float lck = g_logclock[n * HH + h];
        size_t idx = (size_t)n * DD + h * DHD + d;
        float pe = __expf(g_p[idx] + lck - gmax);
        pcs += pe;
        gcs += -softplus_fast(g_g[idx]) * ck;
        float gcp = __expf(fminf(fmaxf(gcs, -50.f), 40.f));
        ccs += ck;
        float qv = g_q[idx], kv = g_k[idx];
        float qp = __shfl_xor_sync(0xffffffffu, qv, 1);
        float kp = __shfl_xor_sync(0xffffffffu, kv, 1);
        float qr = qv * cs_ + sgn * qp * sn_;
        float kr = kv * cs_ + sgn * kp * sn_;
        size_t co = ((size_t)n * HH + h) * DC + d;
        float qs[3], kss[3];
        qs[0] = scale * qr / (pcs + 1e-8f);
        qs[1] = scale * qr * gcp;
        qs[2] = scale * qr / ccs;
        kss[0] = kr * pe;
        kss[1] = kr / (gcp + 1e-8f);
        kss[2] = kr * ck;
#pragma unroll
        for (int j = 0; j < 3; j++) {
            __nv_bfloat16 hq = __float2bfloat16_rn(qs[j]);
            g_qch[co + j * DHD] = hq;
            g_qcl[co + j * DHD] = __float2bfloat16_rn(qs[j] - __bfloat162float(hq));
            __nv_bfloat16 hk = __float2bfloat16_rn(kss[j]);
            g_kch[co + j * DHD] = hk;
            g_kcl[co + j * DHD] = __float2bfloat16_rn(kss[j] - __bfloat162float(hk));
        }
        float nc_ = cs_ * cd - sn_ * sd;
        float ns_ = sn_ * cd + cs_ * sd;
        cs_ = nc_; sn_ = ns_;
    }
}

// ==================== flash attention v4: HMMA + cp.async pipeline ===========
// 8 warps x 16 q-rows = 128 queries per CTA; full 2048-key scan.
#define AT_STG 73728
#define AT_VOFF (2*AT_STG)
#define AT_V 34816
#define AT_SMEM (2*AT_STG + 2*AT_V)   // 217088

__global__ void __launch_bounds__(256, 1) att3()
{
    extern __shared__ char sm[];
    const uint32_t sb = smem_u32(sm);
    const int tid = threadIdx.x, w = tid >> 5, lane = tid & 31;
    const int tq0 = blockIdx.x * 128;
    const int bh = blockIdx.y, b = bh >> 4, h = bh & 15;

    float acco[16][4];
    float m[2] = { -INFINITY, -INFINITY }, l[2] = { 0.f, 0.f };
#pragma unroll
    for (int i = 0; i < 16; i++)
#pragma unroll
        for (int r = 0; r < 4; r++) acco[i][r] = 0.f;

    auto issue_qk = [&](int buf, int s0, int kc) {
        uint32_t base = sb + buf * AT_STG;
#pragma unroll
        for (int i = 0; i < 4; i++) {
            int u = tid + i * 256, row = u >> 3, c8 = u & 7;
            uint32_t off = base + row * 144 + c8 * 16;
            size_t qg = ((size_t)(b * TT + tq0 + row) * HH + h) * DC + kc * 64 + c8 * 8;
            size_t kg = ((size_t)(b * TT + s0 + row) * HH + h) * DC + kc * 64 + c8 * 8;
            CP16(off,         g_qch + qg);
            CP16(off + 18432, g_qcl + qg);
            CP16(off + 36864, g_kch + kg);
            CP16(off + 55296, g_kcl + kg);
        }
    };

    for (int s0 = 0; s0 < TT; s0 += 128) {
#pragma unroll
        for (int i = 0; i < 8; i++) {
            int u = tid + i * 256, row = u >> 4, c16 = u & 15;
            uint32_t off = sb + AT_VOFF + row * 272 + c16 * 16;
            size_t vg = (size_t)(b * TT + s0 + row) * DD + h * 128 + c16 * 8;
            CP16(off,        g_vh + vg);
            CP16(off + AT_V, g_vl + vg);
        }
        issue_qk(0, s0, 0); CP_COMMIT();
        issue_qk(1, s0, 1); CP_COMMIT();

        float accs[16][4];
#pragma unroll
        for (int i = 0; i < 16; i++)
#pragma unroll
            for (int r = 0; r < 4; r++) accs[i][r] = 0.f;

        for (int kc = 0; kc < 6; kc++) {
            if (kc < 5) { CP_WAIT1(); } else { CP_WAIT0(); }
            __syncthreads();
            uint32_t base = sb + (kc & 1) * AT_STG;
#pragma unroll
            for (int ks = 0; ks < 4; ks++) {
                uint32_t aH[4], aL[4];
                uint32_t aa = base + (w * 16 + (lane & 15)) * 144 + ks * 32 + (lane >> 4) * 16;
                ldsm4(aH, aa);
                ldsm4(aL, aa + 18432);
#pragma unroll
                for (int nf2 = 0; nf2 < 8; nf2++) {
                    uint32_t bH[4], bL[4];
                    uint32_t ba = base + 36864
                                + (nf2 * 16 + (lane & 7) + ((lane >> 4) << 3)) * 144
                                + ks * 32 + ((lane >> 3) & 1) * 16;
                    ldsm4(bH, ba);
                    ldsm4(bL, ba + 18432);
                    mma_bf(accs[2 * nf2],     aH, bH[0], bH[1]);
                    mma_bf(accs[2 * nf2 + 1], aH, bH[2], bH[3]);
                    mma_bf(accs[2 * nf2],     aH, bL[0], bL[1]);
                    mma_bf(accs[2 * nf2 + 1], aH, bL[2], bL[3]);
                    mma_bf(accs[2 * nf2],     aL, bH[0], bH[1]);
                    mma_bf(accs[2 * nf2 + 1], aL, bH[2], bH[3]);
                }
            }
            __syncthreads();
            if (kc + 2 < 6) { issue_qk(kc & 1, s0, kc + 2); CP_COMMIT(); }
        }

#pragma unroll
        for (int hf = 0; hf < 2; hf++) {
            float mt = -INFINITY;
#pragma unroll
            for (int nf = 0; nf < 16; nf++)
                mt = fmaxf(mt, fmaxf(accs[nf][2 * hf], accs[nf][2 * hf + 1]));
            mt = fmaxf(mt, __shfl_xor_sync(0xffffffffu, mt, 1));
            mt = fmaxf(mt, __shfl_xor_sync(0xffffffffu, mt, 2));
            float mn = fmaxf(m[hf], mt);
            float corr = __expf(m[hf] - mn);
            float ls = 0.f;
#pragma unroll
            for (int nf = 0; nf < 16; nf++) {
                float p0 = __expf(accs[nf][2 * hf] - mn);
                float p1 = __expf(accs[nf][2 * hf + 1] - mn);
                accs[nf][2 * hf] = p0; accs[nf][2 * hf + 1] = p1;
                ls += p0 + p1;
            }
            ls += __shfl_xor_sync(0xffffffffu, ls, 1);
            ls += __shfl_xor_sync(0xffffffffu, ls, 2);
            l[hf] = l[hf] * corr + ls;
            m[hf] = mn;
#pragma unroll
            for (int nf = 0; nf < 16; nf++) {
                acco[nf][2 * hf]     *= corr;
                acco[nf][2 * hf + 1] *= corr;
            }
        }

        uint32_t ph[8][4], pl[8][4];
#pragma unroll
        for (int kf = 0; kf < 8; kf++) {
            packsplit(accs[2 * kf][0],     accs[2 * kf][1],     ph[kf][0], pl[kf][0]);
            packsplit(accs[2 * kf][2],     accs[2 * kf][3],     ph[kf][1], pl[kf][1]);
            packsplit(accs[2 * kf + 1][0], accs[2 * kf + 1][1], ph[kf][2], pl[kf][2]);
            packsplit(accs[2 * kf + 1][2], accs[2 * kf + 1][3], ph[kf][3], pl[kf][3]);
        }

#pragma unroll
        for (int nf2 = 0; nf2 < 8; nf2++) {
#pragma unroll
            for (int kf = 0; kf < 8; kf++) {
                uint32_t vH[4], vL[4];
                uint32_t va = sb + AT_VOFF
                            + (kf * 16 + (lane & 7) + (((lane >> 3) & 1) << 3)) * 272
                            + (nf2 * 16 + ((lane >> 4) << 3)) * 2;
                ldsm4t(vH, va);
                ldsm4t(vL, va + AT_V);
                mma_bf(acco[2 * nf2],     ph[kf], vH[0], vH[1]);
                mma_bf(acco[2 * nf2 + 1], ph[kf], vH[2], vH[3]);
                mma_bf(acco[2 * nf2],     ph[kf], vL[0], vL[1]);
                mma_bf(acco[2 * nf2 + 1], ph[kf], vL[2], vL[3]);
                mma_bf(acco[2 * nf2],     pl[kf], vH[0], vH[1]);
                mma_bf(acco[2 * nf2 + 1], pl[kf], vH[2], vH[3]);
            }
        }
        __syncthreads();
    }

    // ---- epilogue: write O as bf16 hi/lo (feeds final GEMM directly) ----
    float i0 = 1.f / l[0], i1 = 1.f / l[1];
    int r0 = b * TT + tq0 + w * 16 + (lane >> 2);
#pragma unroll
    for (int nf = 0; nf < 16; nf++) {
        int col = h * 128 + nf * 8 + 2 * (lane & 3);
        size_t o0 = (size_t)r0 * DD + col;
        size_t o1 = o0 + (size_t)8 * DD;
        uint32_t hi, lo;
        packsplit(acco[nf][0] * i0, acco[nf][1] * i0, hi, lo);
        *(uint32_t*)(g_ah + o0) = hi; *(uint32_t*)(g_al + o0) = lo;
        packsplit(acco[nf][2] * i1, acco[nf][3] * i1, hi, lo);
        *(uint32_t*)(g_ah + o1) = hi; *(uint32_t*)(g_al + o1) = lo;
    }
}

// ---------------- launch ----------------------------------------------------
extern "C" void kernel_launch(void* const* d_in, const int* in_sizes, int n_in,
                              void* d_out, int out_size)
{
    const float* x   = (const float*)d_in[0];
    const float* Wq  = (const float*)d_in[1];
    const float* Wk  = (const float*)d_in[2];
    const float* Wv  = (const float*)d_in[3];
    const float* Wg  = (const float*)d_in[4];
    const float* Wp  = (const float*)d_in[5];
    const float* Wcl = (const float*)d_in[6];
    const float* Wc  = (const float*)d_in[7];
    float* out = (float*)d_out;

    __nv_bfloat16 *pxh, *pxl, *pah, *pal, *pwth, *pwtl, *pwch, *pwcl;
    cudaGetSymbolAddress((void**)&pxh, g_xh);
    cudaGetSymbolAddress((void**)&pxl, g_xl);
    cudaGetSymbolAddress((void**)&pah, g_ah);
    cudaGetSymbolAddress((void**)&pal, g_al);
    cudaGetSymbolAddress((void**)&pwth, g_wth);
    cudaGetSymbolAddress((void**)&pwtl, g_wtl);
    cudaGetSymbolAddress((void**)&pwch, g_wch);
    cudaGetSymbolAddress((void**)&pwcl, g_wcl);

    cudaFuncSetAttribute(tgemm_mma, cudaFuncAttributeMaxDynamicSharedMemorySize, GM_SMEM);
    cudaFuncSetAttribute(att3, cudaFuncAttributeMaxDynamicSharedMemorySize, AT_SMEM);

    // launches 1-3: prep. Launches #4/#5 are the two fused-GEMM halves so the
    // profiler lands on tgemm_mma (to verify the fragment-pipeline change).
    conv_split<<<(NROWS * DD / 4 + 255) / 256, 256>>>(
        (const float4*)x, (uint2*)pxh, (uint2*)pxl, NROWS * DD / 4);          // 1
    build_wclk<<<(128 * DD) / 256, 256>>>(Wcl);                               // 2
    W6 ws; ws.w[0] = Wq; ws.w[1] = Wk; ws.w[2] = Wv; ws.w[3] = Wp;
    ws.w[4] = Wg; ws.w[5] = Wc;
    trans_split6<<<dim3(DD / 32, DD / 32, 6), 256>>>(ws, pwth, pwtl, pwch, pwcl); // 3

    // fused projection GEMM: 5 weights + clock head (N = 10368)
    tgemm_mma<<<dim3(41, NROWS / 128), 256, GM_SMEM>>>(
        pxh, pxl, pwth, pwtl, (float*)nullptr, 1, 0);                         // 4
    tgemm_mma<<<dim3(40, NROWS / 128), 256, GM_SMEM>>>(
        pxh, pxl, pwth, pwtl, (float*)nullptr, 1, 41);                        // 5

    scan_phase1<<<dim3(NC, BB * HH), 128>>>();
    scan_phase3<<<dim3(NC, BB * HH), 128>>>();   // phase 2 fused in

    att3<<<dim3(TT / 128, BB * HH), 256, AT_SMEM>>>();

    tgemm_mma<<<dim3(DD / 128, NROWS / 128), 256, GM_SMEM>>>(
        pah, pal, pwch, pwcl, out, 0, 0);
}